// round 16
// baseline (speedup 1.0000x reference)
#include <cuda_runtime.h>
#include <cuda_fp16.h>
#include <math.h>
#include <stdint.h>

#define BN 8192
#define DK 256
#define NTILES 64
#define NPAIRS 2080                     // NTILES*(NTILES+1)/2
#define EXPC 20.6099132090f             // (1/0.07) * log2(e)

// ---------------- static device scratch ----------------
__device__ __align__(16) __half g_znh[BN * DK];   // fp16 normalized z_flowed (4 MB)
__device__ unsigned char g_ao[BN];                // allones flag per row
__device__ float g_pall[NTILES * BN];             // partial all-sums  [colTile][row]
__device__ float g_ppos[NTILES * BN];             // partial pos-sums  [colTile][row]
__device__ float g_blocksum[32];
__device__ unsigned int g_blockcnt[32];
__device__ unsigned int g_ticket;                 // zero-init; self-resetting
__device__ unsigned int g_ticket2;                // zero-init; self-resetting

__device__ __forceinline__ uint32_t smem_u32(const void* p) {
    uint32_t a;
    asm("{ .reg .u64 t; cvta.to.shared.u64 t, %1; cvt.u32.u64 %0, t; }" : "=r"(a) : "l"(p));
    return a;
}
__device__ __forceinline__ void ldsm_x4(uint32_t& r0, uint32_t& r1, uint32_t& r2, uint32_t& r3,
                                        uint32_t addr) {
    asm volatile("ldmatrix.sync.aligned.m8n8.x4.shared.b16 {%0,%1,%2,%3}, [%4];"
                 : "=r"(r0), "=r"(r1), "=r"(r2), "=r"(r3) : "r"(addr));
}
__device__ __forceinline__ void mma16816_f16(uint32_t* d, const uint32_t* a,
                                             uint32_t b0, uint32_t b1) {
    asm volatile(
        "mma.sync.aligned.m16n8k16.row.col.f16.f16.f16.f16 "
        "{%0,%1}, {%2,%3,%4,%5}, {%6,%7}, {%0,%1};"
        : "+r"(d[0]), "+r"(d[1])
        : "r"(a[0]), "r"(a[1]), "r"(a[2]), "r"(a[3]), "r"(b0), "r"(b1));
}
__device__ __forceinline__ void cp16(uint32_t dst, const void* src) {
    asm volatile("cp.async.cg.shared.global [%0], [%1], 16;" :: "r"(dst), "l"(src) : "memory");
}
#define CP_COMMIT() asm volatile("cp.async.commit_group;" ::: "memory")
#define CP_WAIT(n)  asm volatile("cp.async.wait_group %0;" :: "n"(n) : "memory")

// smem layout (dynamic)
#define OFF_MI    0        // 128 floats: i-row mask (0/1)
#define OFF_MJ    512      // 128 floats: j-row mask
#define OFF_RPA   1024     // [4][128] f32
#define OFF_RPP   3072
#define OFF_CPA   5120     // [2][128] f32
#define OFF_CPP   6144
#define OFF_A0    8192
#define OFF_B0    24576
#define OFF_A1    40960
#define OFF_B1    57344
#define SMEM_TOTAL 73728

// ---------------- kernel 1: 2-rows-per-warp L2-normalize (fp16 out) + allones ----------------
__global__ void k_norm(const float* __restrict__ zf, const float* __restrict__ attr) {
    const int w = blockIdx.x * 8 + (threadIdx.x >> 5);
    const int lane = threadIdx.x & 31;
    const int r0 = w * 2, r1 = w * 2 + 1;
    const float4* s0 = reinterpret_cast<const float4*>(zf + r0 * DK);
    const float4* s1 = reinterpret_cast<const float4*>(zf + r1 * DK);
    float4 a0 = s0[lane * 2], a1 = s0[lane * 2 + 1];
    float4 b0 = s1[lane * 2], b1 = s1[lane * 2 + 1];
    float sa = a0.x*a0.x + a0.y*a0.y + a0.z*a0.z + a0.w*a0.w
             + a1.x*a1.x + a1.y*a1.y + a1.z*a1.z + a1.w*a1.w;
    float sb = b0.x*b0.x + b0.y*b0.y + b0.z*b0.z + b0.w*b0.w
             + b1.x*b1.x + b1.y*b1.y + b1.z*b1.z + b1.w*b1.w;
    #pragma unroll
    for (int o = 16; o; o >>= 1) {
        sa += __shfl_xor_sync(0xffffffffu, sa, o);
        sb += __shfl_xor_sync(0xffffffffu, sb, o);
    }
    float ia = rsqrtf(fmaxf(sa, 1e-24f));
    float ib = rsqrtf(fmaxf(sb, 1e-24f));

    __half2 h[4];
    h[0] = __floats2half2_rn(a0.x * ia, a0.y * ia);
    h[1] = __floats2half2_rn(a0.z * ia, a0.w * ia);
    h[2] = __floats2half2_rn(a1.x * ia, a1.y * ia);
    h[3] = __floats2half2_rn(a1.z * ia, a1.w * ia);
    *reinterpret_cast<uint4*>(&g_znh[r0 * DK + lane * 8]) = *reinterpret_cast<uint4*>(h);
    h[0] = __floats2half2_rn(b0.x * ib, b0.y * ib);
    h[1] = __floats2half2_rn(b0.z * ib, b0.w * ib);
    h[2] = __floats2half2_rn(b1.x * ib, b1.y * ib);
    h[3] = __floats2half2_rn(b1.z * ib, b1.w * ib);
    *reinterpret_cast<uint4*>(&g_znh[r1 * DK + lane * 8]) = *reinterpret_cast<uint4*>(h);

    if (lane < 2) {
        int rr = w * 2 + lane;
        const float* a = attr + rr * 4;
        g_ao[rr] = ((a[0] + a[1] + a[2] + a[3]) == 4.0f) ? 1 : 0;
    }
}

// ---- chunk loader ----
__device__ __forceinline__ void load_chunk(uint32_t sbase, uint32_t offA, uint32_t offB,
                                           int i0, int j0, int kc, int tid) {
    #pragma unroll
    for (int u = 0; u < 4; u++) {
        int idx = tid + 256 * u;
        int r = idx >> 3;
        int c = idx & 7;
        int phys = (c ^ r) & 7;
        cp16(sbase + offA + r * 128 + phys * 16, &g_znh[(i0 + r) * DK + kc * 64 + c * 8]);
        cp16(sbase + offB + r * 128 + phys * 16, &g_znh[(j0 + r) * DK + kc * 64 + c * 8]);
    }
    CP_COMMIT();
}

// ---- chunk compute (f16 acc) ----
__device__ __forceinline__ void compute_chunk(uint32_t sbase, uint32_t offA, uint32_t offB,
                                              int wr, int wc, int lane,
                                              uint32_t (&acc)[4][4][2]) {
    #pragma unroll
    for (int kk = 0; kk < 4; kk++) {
        uint32_t afr[4][4], bfr[2][4];
        const int cch = kk * 2 + (lane >> 4);
        #pragma unroll
        for (int mi = 0; mi < 4; mi++) {
            int r = wr * 64 + mi * 16 + (lane & 15);
            int phys = (cch ^ r) & 7;
            ldsm_x4(afr[mi][0], afr[mi][1], afr[mi][2], afr[mi][3],
                    sbase + offA + r * 128 + phys * 16);
        }
        #pragma unroll
        for (int n2 = 0; n2 < 2; n2++) {
            int r = wc * 32 + n2 * 16 + (lane & 15);
            int phys = (cch ^ r) & 7;
            ldsm_x4(bfr[n2][0], bfr[n2][1], bfr[n2][2], bfr[n2][3],
                    sbase + offB + r * 128 + phys * 16);
        }
        #pragma unroll
        for (int mi = 0; mi < 4; mi++)
            #pragma unroll
            for (int ni = 0; ni < 4; ni++) {
                int n2 = ni >> 1, odd = ni & 1;
                mma16816_f16(acc[mi][ni], afr[mi], bfr[n2][odd], bfr[n2][odd + 2]);
            }
    }
}

// epilogue inner loops, diag check optional
#define EPI_LOOP(DIAGCHK)                                                              \
    _Pragma("unroll")                                                                  \
    for (int mi = 0; mi < 4; mi++) {                                                   \
        _Pragma("unroll")                                                              \
        for (int h = 0; h < 2; h++) {                                                  \
            int rloc = wr * 64 + mi * 16 + h * 8 + g;                                  \
            float ai = mI[rloc];                                                       \
            _Pragma("unroll")                                                          \
            for (int ni = 0; ni < 4; ni++) {                                           \
                float2 v = __half22float2(*reinterpret_cast<__half2*>(&acc[mi][ni][h]));\
                _Pragma("unroll")                                                      \
                for (int q = 0; q < 2; q++) {                                          \
                    float e = exp2f((q ? v.y : v.x) * EXPC);                           \
                    if (DIAGCHK) {                                                     \
                        int cloc = wc * 32 + ni * 8 + cp2 + q;                         \
                        if (rloc == cloc) e = 0.f;                                     \
                    }                                                                  \
                    rs[mi * 2 + h] += e;                                               \
                    rp[mi * 2 + h] = fmaf(e, mj[ni * 2 + q], rp[mi * 2 + h]);          \
                    cs[ni * 2 + q] += e;                                               \
                    cpn[ni * 2 + q] = fmaf(e, ai, cpn[ni * 2 + q]);                    \
                }                                                                      \
            }                                                                          \
        }                                                                              \
    }

// ---------------- kernel 2: HMMA gram tile + fused ticket tail ----------------
__global__ __launch_bounds__(256, 2) void k_gram_mma(float* __restrict__ out) {
    extern __shared__ char smem[];
    const int t = blockIdx.x;
    int jt = (int)((sqrtf(8.0f * t + 1.0f) - 1.0f) * 0.5f);
    while ((jt + 1) * (jt + 2) / 2 <= t) jt++;
    while (jt * (jt + 1) / 2 > t) jt--;
    const int it = t - jt * (jt + 1) / 2;

    const uint32_t sbase = smem_u32(smem);
    const int tid = threadIdx.x;
    const int wid = tid >> 5;
    const int lane = tid & 31;
    const int wr = wid & 1;
    const int wc = wid >> 1;
    const int i0 = it * 128, j0 = jt * 128;

    float* mI = reinterpret_cast<float*>(smem + OFF_MI);
    float* mJ = reinterpret_cast<float*>(smem + OFF_MJ);
    if (tid < 128) mI[tid] = g_ao[i0 + tid] ? 1.f : 0.f;
    else           mJ[tid - 128] = g_ao[j0 + (tid - 128)] ? 1.f : 0.f;

    uint32_t acc[4][4][2];
    #pragma unroll
    for (int mi = 0; mi < 4; mi++)
        #pragma unroll
        for (int ni = 0; ni < 4; ni++) { acc[mi][ni][0] = 0u; acc[mi][ni][1] = 0u; }

    load_chunk(sbase, OFF_A0, OFF_B0, i0, j0, 0, tid);
    load_chunk(sbase, OFF_A1, OFF_B1, i0, j0, 1, tid);

    CP_WAIT(1); __syncthreads();
    compute_chunk(sbase, OFF_A0, OFF_B0, wr, wc, lane, acc);
    __syncthreads();
    load_chunk(sbase, OFF_A0, OFF_B0, i0, j0, 2, tid);

    CP_WAIT(1); __syncthreads();
    compute_chunk(sbase, OFF_A1, OFF_B1, wr, wc, lane, acc);
    __syncthreads();
    load_chunk(sbase, OFF_A1, OFF_B1, i0, j0, 3, tid);

    CP_WAIT(1); __syncthreads();
    compute_chunk(sbase, OFF_A0, OFF_B0, wr, wc, lane, acc);

    CP_WAIT(0); __syncthreads();
    compute_chunk(sbase, OFF_A1, OFF_B1, wr, wc, lane, acc);

    // ---- epilogue ----
    const int g = lane >> 2;
    const int cp2 = (lane & 3) * 2;
    float mj[8];
    #pragma unroll
    for (int ni = 0; ni < 4; ni++)
        #pragma unroll
        for (int q = 0; q < 2; q++)
            mj[ni * 2 + q] = mJ[wc * 32 + ni * 8 + cp2 + q];

    float rs[8], rp[8], cs[8], cpn[8];
    #pragma unroll
    for (int x = 0; x < 8; x++) { rs[x] = rp[x] = cs[x] = cpn[x] = 0.f; }

    if (it == jt) { EPI_LOOP(true) } else { EPI_LOOP(false) }

    #pragma unroll
    for (int x = 0; x < 8; x++) {
        rs[x] += __shfl_xor_sync(0xffffffffu, rs[x], 1);
        rs[x] += __shfl_xor_sync(0xffffffffu, rs[x], 2);
        rp[x] += __shfl_xor_sync(0xffffffffu, rp[x], 1);
        rp[x] += __shfl_xor_sync(0xffffffffu, rp[x], 2);
    }
    float* rpa = reinterpret_cast<float*>(smem + OFF_RPA);
    float* rpp = reinterpret_cast<float*>(smem + OFF_RPP);
    if ((lane & 3) == 0) {
        #pragma unroll
        for (int mi = 0; mi < 4; mi++)
            #pragma unroll
            for (int h = 0; h < 2; h++) {
                int rloc = wr * 64 + mi * 16 + h * 8 + g;
                rpa[wc * 128 + rloc] = rs[mi * 2 + h];
                rpp[wc * 128 + rloc] = rp[mi * 2 + h];
            }
    }

    #pragma unroll
    for (int x = 0; x < 8; x++) {
        cs[x]  += __shfl_xor_sync(0xffffffffu, cs[x], 4);
        cs[x]  += __shfl_xor_sync(0xffffffffu, cs[x], 8);
        cs[x]  += __shfl_xor_sync(0xffffffffu, cs[x], 16);
        cpn[x] += __shfl_xor_sync(0xffffffffu, cpn[x], 4);
        cpn[x] += __shfl_xor_sync(0xffffffffu, cpn[x], 8);
        cpn[x] += __shfl_xor_sync(0xffffffffu, cpn[x], 16);
    }
    float* cpa = reinterpret_cast<float*>(smem + OFF_CPA);
    float* cpp = reinterpret_cast<float*>(smem + OFF_CPP);
    if (lane < 4) {
        #pragma unroll
        for (int ni = 0; ni < 4; ni++)
            #pragma unroll
            for (int q = 0; q < 2; q++) {
                int cloc = wc * 32 + ni * 8 + lane * 2 + q;
                cpa[wr * 128 + cloc] = cs[ni * 2 + q];
                cpp[wr * 128 + cloc] = cpn[ni * 2 + q];
            }
    }
    __syncthreads();

    if (tid < 128) {
        float a = rpa[tid] + rpa[128 + tid] + rpa[256 + tid] + rpa[384 + tid];
        float p = rpp[tid] + rpp[128 + tid] + rpp[256 + tid] + rpp[384 + tid];
        g_pall[jt * BN + i0 + tid] = a;
        g_ppos[jt * BN + i0 + tid] = p * mI[tid];
    } else if (it != jt) {
        int j = tid - 128;
        float a = cpa[j] + cpa[128 + j];
        float p = cpp[j] + cpp[128 + j];
        g_pall[it * BN + j0 + j] = a;
        g_ppos[it * BN + j0 + j] = p * mJ[j];
    }

    // ---- fused tail: last 32 finishers adopt one 256-row slice each ----
    __shared__ unsigned int s_ticket;
    __shared__ bool s_last;
    __threadfence();                       // publish partials before ticket
    __syncthreads();
    if (tid == 0) s_ticket = atomicAdd(&g_ticket, 1u) + 1u;
    __syncthreads();
    const unsigned int myt = s_ticket;
    if (myt > NPAIRS - 32) {
        const int slot = NPAIRS - (int)myt;          // 0..31
        if (tid == 0) {
            while (*((volatile unsigned int*)&g_ticket) < NPAIRS) __nanosleep(64);
        }
        __syncthreads();
        __threadfence();                             // order reads after all publishes

        const int i = slot * 256 + tid;
        float all = 0.f, pos = 0.f;
        #pragma unroll 4
        for (int tt = 0; tt < NTILES; tt++) {
            all += g_pall[tt * BN + i];
            pos += g_ppos[tt * BN + i];
        }
        bool valid = (g_ao[i] != 0) && (pos > 0.f);
        float loss = valid ? (logf(all) - logf(pos)) : 0.f;
        unsigned int cnt = valid ? 1u : 0u;
        #pragma unroll
        for (int o = 16; o; o >>= 1) {
            loss += __shfl_xor_sync(0xffffffffu, loss, o);
            cnt  += __shfl_xor_sync(0xffffffffu, cnt, o);
        }
        float* ws = reinterpret_cast<float*>(smem + OFF_RPA);          // reuse smem
        unsigned int* wcv = reinterpret_cast<unsigned int*>(smem + OFF_RPP);
        if ((tid & 31) == 0) { ws[tid >> 5] = loss; wcv[tid >> 5] = cnt; }
        __syncthreads();
        if (tid == 0) {
            float s = 0.f; unsigned int c = 0u;
            #pragma unroll
            for (int k = 0; k < 8; k++) { s += ws[k]; c += wcv[k]; }
            g_blocksum[slot] = s;
            g_blockcnt[slot] = c;
            __threadfence();
            unsigned int t2 = atomicAdd(&g_ticket2, 1u);
            s_last = (t2 == 31u);
        }
        __syncthreads();
        if (s_last && tid < 32) {
            __threadfence();
            float s = g_blocksum[tid];
            unsigned int c = g_blockcnt[tid];
            #pragma unroll
            for (int o = 16; o; o >>= 1) {
                s += __shfl_xor_sync(0xffffffffu, s, o);
                c += __shfl_xor_sync(0xffffffffu, c, o);
            }
            if (tid == 0) {
                out[0] = (c > 0u) ? (s / (float)c) : 0.f;
                g_ticket = 0;                        // reset for next graph replay
                g_ticket2 = 0;
            }
        }
    }
}

// ---------------- entry point ----------------
extern "C" void kernel_launch(void* const* d_in, const int* in_sizes, int n_in,
                              void* d_out, int out_size) {
    const float* zf   = (const float*)d_in[1];
    const float* attr = (const float*)d_in[2];
    float* out = (float*)d_out;

    cudaFuncSetAttribute(k_gram_mma, cudaFuncAttributeMaxDynamicSharedMemorySize, SMEM_TOTAL);

    k_norm<<<BN / 16, 256>>>(zf, attr);
    k_gram_mma<<<NPAIRS, 256, SMEM_TOTAL>>>(out);
}

// round 17
// speedup vs baseline: 1.1984x; 1.1984x over previous
#include <cuda_runtime.h>
#include <cuda_fp16.h>
#include <math.h>
#include <stdint.h>

#define BN 8192
#define DK 256
#define NTILES 64
#define NPAIRS 2080                     // NTILES*(NTILES+1)/2
#define EXPC 20.6099132090f             // (1/0.07) * log2(e)

// ---------------- static device scratch ----------------
__device__ __align__(16) __half g_znh[BN * DK];   // fp16 normalized z_flowed (4 MB)
__device__ unsigned char g_ao[BN];                // allones flag per row
__device__ float g_pall[NTILES * BN];             // partial all-sums  [colTile][row]
__device__ float g_ppos[NTILES * BN];             // partial pos-sums  [colTile][row]
__device__ float g_blocksum[32];
__device__ unsigned int g_blockcnt[32];
__device__ unsigned int g_ticket;                 // zero-init; self-resetting

__device__ __forceinline__ uint32_t smem_u32(const void* p) {
    uint32_t a;
    asm("{ .reg .u64 t; cvta.to.shared.u64 t, %1; cvt.u32.u64 %0, t; }" : "=r"(a) : "l"(p));
    return a;
}
__device__ __forceinline__ void ldsm_x4(uint32_t& r0, uint32_t& r1, uint32_t& r2, uint32_t& r3,
                                        uint32_t addr) {
    asm volatile("ldmatrix.sync.aligned.m8n8.x4.shared.b16 {%0,%1,%2,%3}, [%4];"
                 : "=r"(r0), "=r"(r1), "=r"(r2), "=r"(r3) : "r"(addr));
}
__device__ __forceinline__ void mma16816_f16(uint32_t* d, const uint32_t* a,
                                             uint32_t b0, uint32_t b1) {
    asm volatile(
        "mma.sync.aligned.m16n8k16.row.col.f16.f16.f16.f16 "
        "{%0,%1}, {%2,%3,%4,%5}, {%6,%7}, {%0,%1};"
        : "+r"(d[0]), "+r"(d[1])
        : "r"(a[0]), "r"(a[1]), "r"(a[2]), "r"(a[3]), "r"(b0), "r"(b1));
}
__device__ __forceinline__ void cp16(uint32_t dst, const void* src) {
    asm volatile("cp.async.cg.shared.global [%0], [%1], 16;" :: "r"(dst), "l"(src) : "memory");
}
#define CP_COMMIT() asm volatile("cp.async.commit_group;" ::: "memory")
#define CP_WAIT(n)  asm volatile("cp.async.wait_group %0;" :: "n"(n) : "memory")

// smem layout (dynamic)
#define OFF_MI    0        // 128 floats: i-row mask (0/1)
#define OFF_MJ    512      // 128 floats: j-row mask
#define OFF_RPA   1024     // [4][128] f32
#define OFF_RPP   3072
#define OFF_CPA   5120     // [2][128] f32
#define OFF_CPP   6144
#define OFF_A0    8192
#define OFF_B0    24576
#define OFF_A1    40960
#define OFF_B1    57344
#define SMEM_TOTAL 73728

// ---------------- kernel 1: 2-rows-per-warp L2-normalize (fp16 out) + allones ----------------
__global__ void k_norm(const float* __restrict__ zf, const float* __restrict__ attr) {
    const int w = blockIdx.x * 8 + (threadIdx.x >> 5);
    const int lane = threadIdx.x & 31;
    const int r0 = w * 2, r1 = w * 2 + 1;
    const float4* s0 = reinterpret_cast<const float4*>(zf + r0 * DK);
    const float4* s1 = reinterpret_cast<const float4*>(zf + r1 * DK);
    float4 a0 = s0[lane * 2], a1 = s0[lane * 2 + 1];
    float4 b0 = s1[lane * 2], b1 = s1[lane * 2 + 1];
    float sa = a0.x*a0.x + a0.y*a0.y + a0.z*a0.z + a0.w*a0.w
             + a1.x*a1.x + a1.y*a1.y + a1.z*a1.z + a1.w*a1.w;
    float sb = b0.x*b0.x + b0.y*b0.y + b0.z*b0.z + b0.w*b0.w
             + b1.x*b1.x + b1.y*b1.y + b1.z*b1.z + b1.w*b1.w;
    #pragma unroll
    for (int o = 16; o; o >>= 1) {
        sa += __shfl_xor_sync(0xffffffffu, sa, o);
        sb += __shfl_xor_sync(0xffffffffu, sb, o);
    }
    float ia = rsqrtf(fmaxf(sa, 1e-24f));
    float ib = rsqrtf(fmaxf(sb, 1e-24f));

    __half2 h[4];
    h[0] = __floats2half2_rn(a0.x * ia, a0.y * ia);
    h[1] = __floats2half2_rn(a0.z * ia, a0.w * ia);
    h[2] = __floats2half2_rn(a1.x * ia, a1.y * ia);
    h[3] = __floats2half2_rn(a1.z * ia, a1.w * ia);
    *reinterpret_cast<uint4*>(&g_znh[r0 * DK + lane * 8]) = *reinterpret_cast<uint4*>(h);
    h[0] = __floats2half2_rn(b0.x * ib, b0.y * ib);
    h[1] = __floats2half2_rn(b0.z * ib, b0.w * ib);
    h[2] = __floats2half2_rn(b1.x * ib, b1.y * ib);
    h[3] = __floats2half2_rn(b1.z * ib, b1.w * ib);
    *reinterpret_cast<uint4*>(&g_znh[r1 * DK + lane * 8]) = *reinterpret_cast<uint4*>(h);

    if (lane < 2) {
        int rr = w * 2 + lane;
        const float* a = attr + rr * 4;
        g_ao[rr] = ((a[0] + a[1] + a[2] + a[3]) == 4.0f) ? 1 : 0;
    }
}

// ---- chunk loader ----
__device__ __forceinline__ void load_chunk(uint32_t sbase, uint32_t offA, uint32_t offB,
                                           int i0, int j0, int kc, int tid) {
    #pragma unroll
    for (int u = 0; u < 4; u++) {
        int idx = tid + 256 * u;
        int r = idx >> 3;
        int c = idx & 7;
        int phys = (c ^ r) & 7;
        cp16(sbase + offA + r * 128 + phys * 16, &g_znh[(i0 + r) * DK + kc * 64 + c * 8]);
        cp16(sbase + offB + r * 128 + phys * 16, &g_znh[(j0 + r) * DK + kc * 64 + c * 8]);
    }
    CP_COMMIT();
}

// ---- chunk compute (f16 acc) ----
__device__ __forceinline__ void compute_chunk(uint32_t sbase, uint32_t offA, uint32_t offB,
                                              int wr, int wc, int lane,
                                              uint32_t (&acc)[4][4][2]) {
    #pragma unroll
    for (int kk = 0; kk < 4; kk++) {
        uint32_t afr[4][4], bfr[2][4];
        const int cch = kk * 2 + (lane >> 4);
        #pragma unroll
        for (int mi = 0; mi < 4; mi++) {
            int r = wr * 64 + mi * 16 + (lane & 15);
            int phys = (cch ^ r) & 7;
            ldsm_x4(afr[mi][0], afr[mi][1], afr[mi][2], afr[mi][3],
                    sbase + offA + r * 128 + phys * 16);
        }
        #pragma unroll
        for (int n2 = 0; n2 < 2; n2++) {
            int r = wc * 32 + n2 * 16 + (lane & 15);
            int phys = (cch ^ r) & 7;
            ldsm_x4(bfr[n2][0], bfr[n2][1], bfr[n2][2], bfr[n2][3],
                    sbase + offB + r * 128 + phys * 16);
        }
        #pragma unroll
        for (int mi = 0; mi < 4; mi++)
            #pragma unroll
            for (int ni = 0; ni < 4; ni++) {
                int n2 = ni >> 1, odd = ni & 1;
                mma16816_f16(acc[mi][ni], afr[mi], bfr[n2][odd], bfr[n2][odd + 2]);
            }
    }
}

// epilogue inner loops, diag check optional
#define EPI_LOOP(DIAGCHK)                                                              \
    _Pragma("unroll")                                                                  \
    for (int mi = 0; mi < 4; mi++) {                                                   \
        _Pragma("unroll")                                                              \
        for (int h = 0; h < 2; h++) {                                                  \
            int rloc = wr * 64 + mi * 16 + h * 8 + g;                                  \
            float ai = mI[rloc];                                                       \
            _Pragma("unroll")                                                          \
            for (int ni = 0; ni < 4; ni++) {                                           \
                float2 v = __half22float2(*reinterpret_cast<__half2*>(&acc[mi][ni][h]));\
                _Pragma("unroll")                                                      \
                for (int q = 0; q < 2; q++) {                                          \
                    float e = exp2f((q ? v.y : v.x) * EXPC);                           \
                    if (DIAGCHK) {                                                     \
                        int cloc = wc * 32 + ni * 8 + cp2 + q;                         \
                        if (rloc == cloc) e = 0.f;                                     \
                    }                                                                  \
                    rs[mi * 2 + h] += e;                                               \
                    rp[mi * 2 + h] = fmaf(e, mj[ni * 2 + q], rp[mi * 2 + h]);          \
                    cs[ni * 2 + q] += e;                                               \
                    cpn[ni * 2 + q] = fmaf(e, ai, cpn[ni * 2 + q]);                    \
                }                                                                      \
            }                                                                          \
        }                                                                              \
    }

// ---------------- kernel 2: HMMA gram tile, 3 CTAs/SM ----------------
__global__ __launch_bounds__(256, 3) void k_gram_mma() {
    extern __shared__ char smem[];
    const int t = blockIdx.x;
    int jt = (int)((sqrtf(8.0f * t + 1.0f) - 1.0f) * 0.5f);
    while ((jt + 1) * (jt + 2) / 2 <= t) jt++;
    while (jt * (jt + 1) / 2 > t) jt--;
    const int it = t - jt * (jt + 1) / 2;

    const uint32_t sbase = smem_u32(smem);
    const int tid = threadIdx.x;
    const int wid = tid >> 5;
    const int lane = tid & 31;
    const int wr = wid & 1;
    const int wc = wid >> 1;
    const int i0 = it * 128, j0 = jt * 128;

    float* mI = reinterpret_cast<float*>(smem + OFF_MI);
    float* mJ = reinterpret_cast<float*>(smem + OFF_MJ);
    if (tid < 128) mI[tid] = g_ao[i0 + tid] ? 1.f : 0.f;
    else           mJ[tid - 128] = g_ao[j0 + (tid - 128)] ? 1.f : 0.f;

    uint32_t acc[4][4][2];
    #pragma unroll
    for (int mi = 0; mi < 4; mi++)
        #pragma unroll
        for (int ni = 0; ni < 4; ni++) { acc[mi][ni][0] = 0u; acc[mi][ni][1] = 0u; }

    load_chunk(sbase, OFF_A0, OFF_B0, i0, j0, 0, tid);
    load_chunk(sbase, OFF_A1, OFF_B1, i0, j0, 1, tid);

    CP_WAIT(1); __syncthreads();
    compute_chunk(sbase, OFF_A0, OFF_B0, wr, wc, lane, acc);
    __syncthreads();
    load_chunk(sbase, OFF_A0, OFF_B0, i0, j0, 2, tid);

    CP_WAIT(1); __syncthreads();
    compute_chunk(sbase, OFF_A1, OFF_B1, wr, wc, lane, acc);
    __syncthreads();
    load_chunk(sbase, OFF_A1, OFF_B1, i0, j0, 3, tid);

    CP_WAIT(1); __syncthreads();
    compute_chunk(sbase, OFF_A0, OFF_B0, wr, wc, lane, acc);

    CP_WAIT(0); __syncthreads();
    compute_chunk(sbase, OFF_A1, OFF_B1, wr, wc, lane, acc);

    // ---- epilogue ----
    const int g = lane >> 2;
    const int cp2 = (lane & 3) * 2;
    float mj[8];
    #pragma unroll
    for (int ni = 0; ni < 4; ni++)
        #pragma unroll
        for (int q = 0; q < 2; q++)
            mj[ni * 2 + q] = mJ[wc * 32 + ni * 8 + cp2 + q];

    float rs[8], rp[8], cs[8], cpn[8];
    #pragma unroll
    for (int x = 0; x < 8; x++) { rs[x] = rp[x] = cs[x] = cpn[x] = 0.f; }

    if (it == jt) { EPI_LOOP(true) } else { EPI_LOOP(false) }

    #pragma unroll
    for (int x = 0; x < 8; x++) {
        rs[x] += __shfl_xor_sync(0xffffffffu, rs[x], 1);
        rs[x] += __shfl_xor_sync(0xffffffffu, rs[x], 2);
        rp[x] += __shfl_xor_sync(0xffffffffu, rp[x], 1);
        rp[x] += __shfl_xor_sync(0xffffffffu, rp[x], 2);
    }
    float* rpa = reinterpret_cast<float*>(smem + OFF_RPA);
    float* rpp = reinterpret_cast<float*>(smem + OFF_RPP);
    if ((lane & 3) == 0) {
        #pragma unroll
        for (int mi = 0; mi < 4; mi++)
            #pragma unroll
            for (int h = 0; h < 2; h++) {
                int rloc = wr * 64 + mi * 16 + h * 8 + g;
                rpa[wc * 128 + rloc] = rs[mi * 2 + h];
                rpp[wc * 128 + rloc] = rp[mi * 2 + h];
            }
    }

    #pragma unroll
    for (int x = 0; x < 8; x++) {
        cs[x]  += __shfl_xor_sync(0xffffffffu, cs[x], 4);
        cs[x]  += __shfl_xor_sync(0xffffffffu, cs[x], 8);
        cs[x]  += __shfl_xor_sync(0xffffffffu, cs[x], 16);
        cpn[x] += __shfl_xor_sync(0xffffffffu, cpn[x], 4);
        cpn[x] += __shfl_xor_sync(0xffffffffu, cpn[x], 8);
        cpn[x] += __shfl_xor_sync(0xffffffffu, cpn[x], 16);
    }
    float* cpa = reinterpret_cast<float*>(smem + OFF_CPA);
    float* cpp = reinterpret_cast<float*>(smem + OFF_CPP);
    if (lane < 4) {
        #pragma unroll
        for (int ni = 0; ni < 4; ni++)
            #pragma unroll
            for (int q = 0; q < 2; q++) {
                int cloc = wc * 32 + ni * 8 + lane * 2 + q;
                cpa[wr * 128 + cloc] = cs[ni * 2 + q];
                cpp[wr * 128 + cloc] = cpn[ni * 2 + q];
            }
    }
    __syncthreads();

    if (tid < 128) {
        float a = rpa[tid] + rpa[128 + tid] + rpa[256 + tid] + rpa[384 + tid];
        float p = rpp[tid] + rpp[128 + tid] + rpp[256 + tid] + rpp[384 + tid];
        g_pall[jt * BN + i0 + tid] = a;
        g_ppos[jt * BN + i0 + tid] = p * mI[tid];
    } else if (it != jt) {
        int j = tid - 128;
        float a = cpa[j] + cpa[128 + j];
        float p = cpp[j] + cpp[128 + j];
        g_pall[it * BN + j0 + j] = a;
        g_ppos[it * BN + j0 + j] = p * mJ[j];
    }
}

// ---------------- kernel 3: per-row loss + last-block final reduction ----------------
__global__ void k_rowloss_final(float* __restrict__ out) {
    int i = blockIdx.x * blockDim.x + threadIdx.x;
    float all = 0.f, pos = 0.f;
    #pragma unroll 4
    for (int t = 0; t < NTILES; t++) {
        all += g_pall[t * BN + i];
        pos += g_ppos[t * BN + i];
    }
    bool valid = (g_ao[i] != 0) && (pos > 0.f);
    float loss = valid ? (logf(all) - logf(pos)) : 0.f;
    unsigned int cnt = valid ? 1u : 0u;
    #pragma unroll
    for (int o = 16; o; o >>= 1) {
        loss += __shfl_xor_sync(0xffffffffu, loss, o);
        cnt  += __shfl_xor_sync(0xffffffffu, cnt, o);
    }
    __shared__ float ws[8];
    __shared__ unsigned int wcv[8];
    __shared__ bool s_last;
    int tid = threadIdx.x;
    if ((tid & 31) == 0) { ws[tid >> 5] = loss; wcv[tid >> 5] = cnt; }
    __syncthreads();
    if (tid == 0) {
        float s = 0.f; unsigned int c = 0u;
        #pragma unroll
        for (int k = 0; k < 8; k++) { s += ws[k]; c += wcv[k]; }
        g_blocksum[blockIdx.x] = s;
        g_blockcnt[blockIdx.x] = c;
        __threadfence();
        unsigned int t = atomicAdd(&g_ticket, 1u);
        s_last = (t == gridDim.x - 1);
    }
    __syncthreads();
    if (s_last && tid < 32) {
        float s = g_blocksum[tid];
        unsigned int c = g_blockcnt[tid];
        #pragma unroll
        for (int o = 16; o; o >>= 1) {
            s += __shfl_xor_sync(0xffffffffu, s, o);
            c += __shfl_xor_sync(0xffffffffu, c, o);
        }
        if (tid == 0) {
            out[0] = (c > 0u) ? (s / (float)c) : 0.f;
            g_ticket = 0;
        }
    }
}

// ---------------- entry point ----------------
extern "C" void kernel_launch(void* const* d_in, const int* in_sizes, int n_in,
                              void* d_out, int out_size) {
    const float* zf   = (const float*)d_in[1];
    const float* attr = (const float*)d_in[2];
    float* out = (float*)d_out;

    cudaFuncSetAttribute(k_gram_mma, cudaFuncAttributeMaxDynamicSharedMemorySize, SMEM_TOTAL);

    k_norm<<<BN / 16, 256>>>(zf, attr);
    k_gram_mma<<<NPAIRS, 256, SMEM_TOTAL>>>();
    k_rowloss_final<<<BN / 256, 256>>>(out);
}